// round 1
// baseline (speedup 1.0000x reference)
#include <cuda_runtime.h>
#include <cuda_bf16.h>
#include <cstdint>

// Problem constants
#define NN      50000        // nodes
#define EE      800000       // edges
#define MM      (EE + NN)    // edges + self loops
#define DD      64           // feature dim (in == out)
#define HH      8            // heads
#define RP1     9            // relations + 1 (self-loop relation = 8)
#define NEG_SLOPE 0.2f
#define EPSV    1e-10f

// Scratch (device globals: allocation-free per harness rules)
__device__ float g_hidden[(size_t)RP1 * NN * DD];  // 115.2 MB, ~fits L2
__device__ float g_sum[NN * HH];                   // per (node, head) sum of e
__device__ float g_um[NN * DD];                    // unnormalized message sum
__device__ float g_cnt[NN];                        // incident edge count

// ---------------------------------------------------------------------------
// K0: zero the accumulators
// ---------------------------------------------------------------------------
__global__ void k_zero() {
    int i = blockIdx.x * 256 + threadIdx.x;
    if (i < NN * DD) g_um[i] = 0.f;
    if (i < NN * HH) g_sum[i] = 0.f;
    if (i < NN)      g_cnt[i] = 0.f;
}

// ---------------------------------------------------------------------------
// K1: hidden[r][n][d] = sum_i W_tau[r][d][i] * x[n][i]
// Block: 64 nodes x 64 dims for one relation. blockDim = (64, 4).
// Ws stored transposed [i][d] for conflict-free compute loads; xs broadcast.
// ---------------------------------------------------------------------------
__global__ __launch_bounds__(256) void k_hidden(const float* __restrict__ x,
                                                const float* __restrict__ W_tau) {
    __shared__ float Ws[64][65];
    __shared__ float xs[64][65];
    const int r    = blockIdx.y;
    const int base = blockIdx.x * 64;
    const int tid  = threadIdx.y * 64 + threadIdx.x;

    const float* Wr = W_tau + (size_t)r * 64 * 64;
    #pragma unroll
    for (int k = 0; k < 16; k++) {
        int idx = tid + k * 256;
        int d = idx >> 6, i = idx & 63;
        Ws[i][d] = Wr[idx];
    }
    #pragma unroll
    for (int k = 0; k < 16; k++) {
        int idx = tid + k * 256;
        int row = idx >> 6, col = idx & 63;
        int n = base + row;
        xs[row][col] = (n < NN) ? x[(size_t)n * 64 + col] : 0.f;
    }
    __syncthreads();

    const int d   = threadIdx.x;
    const int sub = threadIdx.y;
    float acc[16];
    #pragma unroll
    for (int k = 0; k < 16; k++) acc[k] = 0.f;

    #pragma unroll 8
    for (int i = 0; i < 64; i++) {
        float wd = Ws[i][d];
        #pragma unroll
        for (int k = 0; k < 16; k++)
            acc[k] += wd * xs[sub * 16 + k][i];
    }

    float* out = g_hidden + ((size_t)r * NN + base) * 64 + d;
    #pragma unroll
    for (int k = 0; k < 16; k++) {
        int n = sub * 16 + k;
        if (base + n < NN) out[(size_t)n * 64] = acc[k];
    }
}

// ---------------------------------------------------------------------------
// K2: fused per-edge attention + scatter.
//   8 threads per edge (one per head). Each thread:
//     gathers h_in/h_out 8-float slices, dots with interleaved query,
//     leaky_relu -> exp -> * edge_weight,
//     red.v4 into g_um, atomicAdd into g_sum, lane h==0 bumps g_cnt.
// Segment-max stabilization cancels in the final ratio and is omitted
// (w has ~unit scale, exp cannot overflow fp32).
// ---------------------------------------------------------------------------
__device__ __forceinline__ void red_add_v4(float* p, float a, float b, float c, float d) {
    asm volatile("red.global.add.v4.f32 [%0], {%1,%2,%3,%4};"
                 :: "l"(p), "f"(a), "f"(b), "f"(c), "f"(d) : "memory");
}

__global__ __launch_bounds__(256) void k_edge(const int*   __restrict__ node_in,
                                              const int*   __restrict__ node_out,
                                              const int*   __restrict__ relation,
                                              const float* __restrict__ edge_weight,
                                              const float* __restrict__ query) {
    const int t = blockIdx.x * 256 + threadIdx.x;
    const int m = t >> 3;
    const int h = t & 7;
    if (m >= MM) return;

    int ni, no, r; float ew;
    if (m < EE) {
        ni = node_in[m]; no = node_out[m]; r = relation[m]; ew = edge_weight[m];
    } else {
        ni = no = m - EE; r = RP1 - 1; ew = 1.f;
    }

    const float4* hin  = (const float4*)(g_hidden + ((size_t)r * NN + ni) * 64 + h * 8);
    const float4* hout = (const float4*)(g_hidden + ((size_t)r * NN + no) * 64 + h * 8);
    float4 a0 = hin[0],  a1 = hin[1];
    float4 b0 = hout[0], b1 = hout[1];

    const float4* q = (const float4*)(query + ((size_t)r * HH + h) * 16);
    float4 q0 = q[0], q1 = q[1], q2 = q[2], q3 = q[3];

    // key_feat interleaves (h_in, h_out) pairs: q[2j]*h_in_j + q[2j+1]*h_out_j
    float w = q0.x * a0.x + q0.y * b0.x + q0.z * a0.y + q0.w * b0.y
            + q1.x * a0.z + q1.y * b0.z + q1.z * a0.w + q1.w * b0.w
            + q2.x * a1.x + q2.y * b1.x + q2.z * a1.y + q2.w * b1.y
            + q3.x * a1.z + q3.y * b1.z + q3.z * a1.w + q3.w * b1.w;
    w = (w > 0.f) ? w : NEG_SLOPE * w;
    float e = __expf(w) * ew;

    float* um = g_um + (size_t)no * 64 + h * 8;
    red_add_v4(um,     e * a0.x, e * a0.y, e * a0.z, e * a0.w);
    red_add_v4(um + 4, e * a1.x, e * a1.y, e * a1.z, e * a1.w);
    atomicAdd(&g_sum[no * HH + h], e);
    if (h == 0) atomicAdd(&g_cnt[no], 1.f);
}

// ---------------------------------------------------------------------------
// K3: finalize: out[n,d] = relu( um[n,d] / (sum[n,h] + cnt[n]*eps) )
//   (derivation: update = Sum(e*v)/(Sum(e) + cnt*eps); eps term matches
//    reference's norm+eps with norm = Sum(e)/cnt up to O(1e-7) rel.)
// ---------------------------------------------------------------------------
__global__ void k_final(float* __restrict__ out) {
    int idx = blockIdx.x * 256 + threadIdx.x;
    if (idx >= NN * DD) return;
    int n = idx >> 6;
    int h = (idx & 63) >> 3;
    float denom = g_sum[n * HH + h] + g_cnt[n] * EPSV;
    float v = g_um[idx] / denom;
    out[idx] = v > 0.f ? v : 0.f;
}

// ---------------------------------------------------------------------------
extern "C" void kernel_launch(void* const* d_in, const int* in_sizes, int n_in,
                              void* d_out, int out_size) {
    const float* x           = (const float*)d_in[0];
    const float* W_tau       = (const float*)d_in[1];
    const float* query       = (const float*)d_in[2];
    const int*   node_in     = (const int*)  d_in[3];
    const int*   node_out    = (const int*)  d_in[4];
    const int*   relation    = (const int*)  d_in[5];
    const float* edge_weight = (const float*)d_in[6];
    float*       out         = (float*)d_out;

    // K0: zero accumulators (NN*DD = 3.2M elems dominates)
    k_zero<<<(NN * DD + 255) / 256, 256>>>();

    // K1: per-relation node transform
    dim3 g1((NN + 63) / 64, RP1);
    dim3 b1(64, 4);
    k_hidden<<<g1, b1>>>(x, W_tau);

    // K2: fused edge attention + scatter (8 threads / edge)
    int threads = MM * HH;
    k_edge<<<(threads + 255) / 256, 256>>>(node_in, node_out, relation, edge_weight, query);

    // K3: finalize
    k_final<<<(NN * DD + 255) / 256, 256>>>(out);
}

// round 4
// speedup vs baseline: 1.3605x; 1.3605x over previous
#include <cuda_runtime.h>
#include <cuda_bf16.h>
#include <cstdint>

// Problem constants
#define NN      50000        // nodes
#define EE      800000       // edges
#define MM      (EE + NN)    // edges + self loops
#define HH      8            // heads
#define RP1     9            // relations + 1 (self-loop relation = 8)
#define NEG_SLOPE 0.2f

#define NB      80           // GEMM N: 64 hidden dims + 8 s_in + 8 s_out
#define NPAD    50048        // 782 * 64
#define MT      782          // ceil(NN / 64)

// ---------------------------------------------------------------------------
// Scratch (device globals; allocation-free per harness rules)
// ---------------------------------------------------------------------------
__device__ float          g_hidden[(size_t)RP1 * NN * 64];  // 115.2 MB
__device__ float          g_s[(size_t)RP1 * NN * 16];       // s_in[0..7] | s_out[8..15]
__device__ float          g_sum[NN * HH];
__device__ float          g_um[NN * 64];
__device__ __nv_bfloat16  g_xs[(size_t)NPAD * 128];         // x hi|lo bf16, K=128
__device__ __nv_bfloat16  g_B[RP1 * NB * 128];              // B' hi|lo bf16

// ---------------------------------------------------------------------------
__device__ __forceinline__ uint32_t smem_u32(const void* p) {
    uint32_t a;
    asm("{ .reg .u64 t; cvta.to.shared.u64 t, %1; cvt.u32.u64 %0, t; }"
        : "=r"(a) : "l"(p));
    return a;
}

__device__ __forceinline__ void mma_bf16(float* c, uint32_t a0, uint32_t a1,
                                         uint32_t a2, uint32_t a3,
                                         uint32_t b0, uint32_t b1) {
    asm volatile(
        "mma.sync.aligned.m16n8k16.row.col.f32.bf16.bf16.f32 "
        "{%0,%1,%2,%3}, {%4,%5,%6,%7}, {%8,%9}, {%0,%1,%2,%3};"
        : "+f"(c[0]), "+f"(c[1]), "+f"(c[2]), "+f"(c[3])
        : "r"(a0), "r"(a1), "r"(a2), "r"(a3), "r"(b0), "r"(b1));
}

__device__ __forceinline__ uint32_t pack_bf2(float a, float b) {
    __nv_bfloat162 p = __halves2bfloat162(__float2bfloat16(a), __float2bfloat16(b));
    return *(uint32_t*)&p;
}

// ---------------------------------------------------------------------------
// K0: zero accumulators
// ---------------------------------------------------------------------------
__global__ void k_zero() {
    int i = blockIdx.x * 256 + threadIdx.x;
    if (i < NN * 16) ((float4*)g_um)[i]  = make_float4(0.f, 0.f, 0.f, 0.f);
    if (i < NN * 2)  ((float4*)g_sum)[i] = make_float4(0.f, 0.f, 0.f, 0.f);
}

// ---------------------------------------------------------------------------
// KpX: split x into bf16 hi|lo rows of K=128 (hi at k<64, lo at k+64).
// ---------------------------------------------------------------------------
__global__ void k_prepX(const float* __restrict__ x) {
    int i = blockIdx.x * 256 + threadIdx.x;
    if (i >= NPAD * 8) return;
    int n = i >> 3, j = i & 7;
    uint4 hi = make_uint4(0, 0, 0, 0), lo = make_uint4(0, 0, 0, 0);
    if (n < NN) {
        const float4* src = (const float4*)(x + (size_t)n * 64 + j * 8);
        float4 v0 = src[0], v1 = src[1];
        hi.x = pack_bf2(v0.x, v0.y);
        hi.y = pack_bf2(v0.z, v0.w);
        hi.z = pack_bf2(v1.x, v1.y);
        hi.w = pack_bf2(v1.z, v1.w);
        float r0x = v0.x - __bfloat162float(__float2bfloat16(v0.x));
        float r0y = v0.y - __bfloat162float(__float2bfloat16(v0.y));
        float r0z = v0.z - __bfloat162float(__float2bfloat16(v0.z));
        float r0w = v0.w - __bfloat162float(__float2bfloat16(v0.w));
        float r1x = v1.x - __bfloat162float(__float2bfloat16(v1.x));
        float r1y = v1.y - __bfloat162float(__float2bfloat16(v1.y));
        float r1z = v1.z - __bfloat162float(__float2bfloat16(v1.z));
        float r1w = v1.w - __bfloat162float(__float2bfloat16(v1.w));
        lo.x = pack_bf2(r0x, r0y);
        lo.y = pack_bf2(r0z, r0w);
        lo.z = pack_bf2(r1x, r1y);
        lo.w = pack_bf2(r1z, r1w);
    }
    uint4* dst = (uint4*)g_xs;
    dst[(size_t)n * 16 + j]     = hi;
    dst[(size_t)n * 16 + 8 + j] = lo;
}

// ---------------------------------------------------------------------------
// KpW: B' = [W_tau rows | q_even-folded | q_odd-folded], bf16 hi|lo (K=128).
// ---------------------------------------------------------------------------
__global__ void k_prepW(const float* __restrict__ W, const float* __restrict__ query) {
    int r = blockIdx.x;
    int row = threadIdx.x;                 // 0..79
    const float* Wr = W + (size_t)r * 64 * 64;
    __nv_bfloat16* b = g_B + ((size_t)r * NB + row) * 128;
    for (int i = 0; i < 64; i++) {
        float v;
        if (row < 64) {
            v = Wr[row * 64 + i];
        } else {
            int h = (row - 64) & 7;
            int par = (row - 64) >> 3;     // 0 = even (s_in), 1 = odd (s_out)
            const float* q = query + ((size_t)r * HH + h) * 16 + par;
            float acc = 0.f;
            #pragma unroll
            for (int j = 0; j < 8; j++) acc += q[2 * j] * Wr[(h * 8 + j) * 64 + i];
            v = acc;
        }
        __nv_bfloat16 hi = __float2bfloat16(v);
        b[i]      = hi;
        b[64 + i] = __float2bfloat16(v - __bfloat162float(hi));
    }
}

// ---------------------------------------------------------------------------
// Kg: mma.sync bf16 GEMM with hi/lo cross terms. CTA = 64 nodes x 80 cols,
//   K = 12 k16-steps pairing A-chunk/B-chunk:
//     hi*hi: (0,0)(1,1)(2,2)(3,3)
//     hi*lo: (0,4)(1,5)(2,6)(3,7)
//     lo*hi: (4,0)(5,1)(6,2)(7,3)    (lo*lo dropped, ~2^-18 rel)
// ---------------------------------------------------------------------------
__global__ __launch_bounds__(128) void k_gemm(int dummy) {
    __shared__ uint8_t  sA[64 * 256];      // 16 KB, swizzled chunks
    __shared__ uint32_t sB[NB * 68];       // 21.76 KB

    const int r     = blockIdx.y;
    const int mbase = blockIdx.x * 64;
    const int tid   = threadIdx.x;

    // ---- A: 64 rows x 256B; thread t loads half a row (8 uint4) ----
    {
        int row = tid >> 1, half = tid & 1;
        const uint4* src = (const uint4*)(g_xs + (size_t)(mbase + row) * 128) + half * 8;
        #pragma unroll
        for (int j = 0; j < 8; j++) {
            int chunk = half * 8 + j;
            *(uint4*)(sA + row * 256 + (((chunk ^ (row & 7))) << 4)) = src[j];
        }
    }
    // ---- B: 80 rows x 16 chunks -> stride-68 u32 rows ----
    {
        const uint4* src = (const uint4*)(g_B + (size_t)r * NB * 128);
        #pragma unroll
        for (int j = 0; j < 10; j++) {
            int c = tid + j * 128;         // 0..1279
            int row = c >> 4, w = c & 15;
            *(uint4*)(sB + row * 68 + w * 4) = src[c];
        }
    }
    __syncthreads();

    const int warp = tid >> 5, lane = tid & 31;
    const int g = lane >> 2, t = lane & 3;

    float acc[40];
    #pragma unroll
    for (int i = 0; i < 40; i++) acc[i] = 0.f;

    const int rowl = warp * 16 + ((lane >> 3) & 1) * 8 + (lane & 7);
    const int chs  = lane >> 4;

    const int stepA[12] = {0, 1, 2, 3, 0, 1, 2, 3, 4, 5, 6, 7};
    const int stepB[12] = {0, 1, 2, 3, 4, 5, 6, 7, 0, 1, 2, 3};

    #pragma unroll
    for (int s = 0; s < 12; s++) {
        const int ca = stepA[s], cb = stepB[s];
        uint32_t a0, a1, a2, a3;
        uint32_t addr = smem_u32(sA + rowl * 256 + (((2 * ca + chs) ^ (rowl & 7)) << 4));
        asm volatile("ldmatrix.sync.aligned.m8n8.x4.shared.b16 {%0,%1,%2,%3}, [%4];"
                     : "=r"(a0), "=r"(a1), "=r"(a2), "=r"(a3) : "r"(addr));
        #pragma unroll
        for (int nt = 0; nt < 10; nt++) {
            uint32_t b0 = sB[(nt * 8 + g) * 68 + cb * 8 + t];
            uint32_t b1 = sB[(nt * 8 + g) * 68 + cb * 8 + t + 4];
            mma_bf16(acc + nt * 4, a0, a1, a2, a3, b0, b1);
        }
    }

    // ---- epilogue: direct STG.64 (rows g, g+8; col pairs nt*8+2t) ----
    #pragma unroll
    for (int half = 0; half < 2; half++) {
        int n = mbase + warp * 16 + g + 8 * half;
        if (n < NN) {
            float* hd = g_hidden + ((size_t)r * NN + n) * 64 + 2 * t;
            #pragma unroll
            for (int nt = 0; nt < 8; nt++)
                *(float2*)(hd + nt * 8) =
                    make_float2(acc[nt * 4 + 2 * half], acc[nt * 4 + 2 * half + 1]);
            float* sd = g_s + ((size_t)r * NN + n) * 16 + 2 * t;
            #pragma unroll
            for (int nt = 8; nt < 10; nt++)
                *(float2*)(sd + (nt - 8) * 8) =
                    make_float2(acc[nt * 4 + 2 * half], acc[nt * 4 + 2 * half + 1]);
        }
    }
}

// ---------------------------------------------------------------------------
// K2: fused edge attention + scatter. 8 threads/edge (one per head).
// ---------------------------------------------------------------------------
__device__ __forceinline__ void red_add_v4(float* p, float a, float b, float c, float d) {
    asm volatile("red.global.add.v4.f32 [%0], {%1,%2,%3,%4};"
                 :: "l"(p), "f"(a), "f"(b), "f"(c), "f"(d) : "memory");
}

__global__ __launch_bounds__(256) void k_edge(const int*   __restrict__ node_in,
                                              const int*   __restrict__ node_out,
                                              const int*   __restrict__ relation,
                                              const float* __restrict__ edge_weight) {
    const int t = blockIdx.x * 256 + threadIdx.x;
    const int m = t >> 3;
    const int h = t & 7;
    if (m >= MM) return;

    int ni, no, r; float ew;
    if (m < EE) {
        ni = node_in[m]; no = node_out[m]; r = relation[m]; ew = edge_weight[m];
    } else {
        ni = no = m - EE; r = RP1 - 1; ew = 1.f;
    }

    const size_t bi = (size_t)r * NN + ni;
    const size_t bo = (size_t)r * NN + no;
    float w = g_s[bi * 16 + h] + g_s[bo * 16 + 8 + h];
    w = (w > 0.f) ? w : NEG_SLOPE * w;
    float e = __expf(w) * ew;

    const float4* hin = (const float4*)(g_hidden + bi * 64 + h * 8);
    float4 a0 = hin[0], a1 = hin[1];

    float* um = g_um + (size_t)no * 64 + h * 8;
    red_add_v4(um,     e * a0.x, e * a0.y, e * a0.z, e * a0.w);
    red_add_v4(um + 4, e * a1.x, e * a1.y, e * a1.z, e * a1.w);
    atomicAdd(&g_sum[no * HH + h], e);
}

// ---------------------------------------------------------------------------
// K3: finalize: out = relu( um / sum )
//   (cnt*eps term <= 1.2e-8 relative — dropped; self-loop guarantees sum>0)
// ---------------------------------------------------------------------------
__global__ void k_final(float4* __restrict__ out) {
    int i = blockIdx.x * 256 + threadIdx.x;
    if (i >= NN * 16) return;
    int n = i >> 4;
    int h = (i & 15) >> 1;
    float inv = 1.f / g_sum[n * HH + h];
    float4 v = ((const float4*)g_um)[i];
    v.x *= inv; v.y *= inv; v.z *= inv; v.w *= inv;
    v.x = v.x > 0.f ? v.x : 0.f;
    v.y = v.y > 0.f ? v.y : 0.f;
    v.z = v.z > 0.f ? v.z : 0.f;
    v.w = v.w > 0.f ? v.w : 0.f;
    out[i] = v;
}

// ---------------------------------------------------------------------------
extern "C" void kernel_launch(void* const* d_in, const int* in_sizes, int n_in,
                              void* d_out, int out_size) {
    const float* x           = (const float*)d_in[0];
    const float* W_tau       = (const float*)d_in[1];
    const float* query       = (const float*)d_in[2];
    const int*   node_in     = (const int*)  d_in[3];
    const int*   node_out    = (const int*)  d_in[4];
    const int*   relation    = (const int*)  d_in[5];
    const float* edge_weight = (const float*)d_in[6];

    k_zero<<<(NN * 16 + 255) / 256, 256>>>();
    k_prepX<<<(NPAD * 8 + 255) / 256, 256>>>(x);
    k_prepW<<<RP1, NB>>>(W_tau, query);

    dim3 gg(MT, RP1);
    k_gemm<<<gg, 128>>>(0);

    k_edge<<<(MM * 8 + 255) / 256, 256>>>(node_in, node_out, relation, edge_weight);

    k_final<<<(NN * 16 + 255) / 256, 256>>>((float4*)d_out);
}

// round 5
// speedup vs baseline: 1.3620x; 1.0011x over previous
#include <cuda_runtime.h>
#include <cuda_bf16.h>
#include <cstdint>

// Problem constants
#define NN      50000        // nodes
#define EE      800000       // edges
#define MM      (EE + NN)    // edges + self loops
#define HH      8            // heads
#define RP1     9            // relations + 1 (self-loop relation = 8)
#define NEG_SLOPE 0.2f

#define NB      80           // GEMM N: 64 hidden dims + 8 s_in + 8 s_out
#define NPAD    50048        // 782 * 64
#define MT      782          // ceil(NN / 64)

// ---------------------------------------------------------------------------
// Scratch (device globals; allocation-free per harness rules)
// ---------------------------------------------------------------------------
__device__ float          g_hidden[(size_t)RP1 * NN * 64];  // 115.2 MB
__device__ float          g_s[(size_t)RP1 * NN * 16];       // s_in[0..7] | s_out[8..15]
__device__ float          g_sum[NN * HH];
__device__ float          g_um[NN * 64];
__device__ __nv_bfloat16  g_xs[(size_t)NPAD * 128];         // x hi|lo bf16, K=128
__device__ __nv_bfloat16  g_B[RP1 * NB * 128];              // B' hi|lo bf16

// ---------------------------------------------------------------------------
__device__ __forceinline__ uint32_t smem_u32(const void* p) {
    uint32_t a;
    asm("{ .reg .u64 t; cvta.to.shared.u64 t, %1; cvt.u32.u64 %0, t; }"
        : "=r"(a) : "l"(p));
    return a;
}

__device__ __forceinline__ void mma_bf16(float* c, uint32_t a0, uint32_t a1,
                                         uint32_t a2, uint32_t a3,
                                         uint32_t b0, uint32_t b1) {
    asm volatile(
        "mma.sync.aligned.m16n8k16.row.col.f32.bf16.bf16.f32 "
        "{%0,%1,%2,%3}, {%4,%5,%6,%7}, {%8,%9}, {%0,%1,%2,%3};"
        : "+f"(c[0]), "+f"(c[1]), "+f"(c[2]), "+f"(c[3])
        : "r"(a0), "r"(a1), "r"(a2), "r"(a3), "r"(b0), "r"(b1));
}

__device__ __forceinline__ uint32_t pack_bf2(float a, float b) {
    __nv_bfloat162 p = __halves2bfloat162(__float2bfloat16(a), __float2bfloat16(b));
    return *(uint32_t*)&p;
}

// ---------------------------------------------------------------------------
// K0: zero accumulators
// ---------------------------------------------------------------------------
__global__ void k_zero() {
    int i = blockIdx.x * 256 + threadIdx.x;
    if (i < NN * 16) ((float4*)g_um)[i]  = make_float4(0.f, 0.f, 0.f, 0.f);
    if (i < NN * 2)  ((float4*)g_sum)[i] = make_float4(0.f, 0.f, 0.f, 0.f);
}

// ---------------------------------------------------------------------------
// KpX: split x into bf16 hi|lo rows of K=128 (hi at k<64, lo at k+64).
// ---------------------------------------------------------------------------
__global__ void k_prepX(const float* __restrict__ x) {
    int i = blockIdx.x * 256 + threadIdx.x;
    if (i >= NPAD * 8) return;
    int n = i >> 3, j = i & 7;
    uint4 hi = make_uint4(0, 0, 0, 0), lo = make_uint4(0, 0, 0, 0);
    if (n < NN) {
        const float4* src = (const float4*)(x + (size_t)n * 64 + j * 8);
        float4 v0 = src[0], v1 = src[1];
        hi.x = pack_bf2(v0.x, v0.y);
        hi.y = pack_bf2(v0.z, v0.w);
        hi.z = pack_bf2(v1.x, v1.y);
        hi.w = pack_bf2(v1.z, v1.w);
        float r0x = v0.x - __bfloat162float(__float2bfloat16(v0.x));
        float r0y = v0.y - __bfloat162float(__float2bfloat16(v0.y));
        float r0z = v0.z - __bfloat162float(__float2bfloat16(v0.z));
        float r0w = v0.w - __bfloat162float(__float2bfloat16(v0.w));
        float r1x = v1.x - __bfloat162float(__float2bfloat16(v1.x));
        float r1y = v1.y - __bfloat162float(__float2bfloat16(v1.y));
        float r1z = v1.z - __bfloat162float(__float2bfloat16(v1.z));
        float r1w = v1.w - __bfloat162float(__float2bfloat16(v1.w));
        lo.x = pack_bf2(r0x, r0y);
        lo.y = pack_bf2(r0z, r0w);
        lo.z = pack_bf2(r1x, r1y);
        lo.w = pack_bf2(r1z, r1w);
    }
    uint4* dst = (uint4*)g_xs;
    dst[(size_t)n * 16 + j]     = hi;
    dst[(size_t)n * 16 + 8 + j] = lo;
}

// ---------------------------------------------------------------------------
// KpW: B' = [W_tau rows | q_even-folded | q_odd-folded], bf16 hi|lo (K=128).
// ---------------------------------------------------------------------------
__global__ void k_prepW(const float* __restrict__ W, const float* __restrict__ query) {
    int r = blockIdx.x;
    int row = threadIdx.x;                 // 0..79
    const float* Wr = W + (size_t)r * 64 * 64;
    __nv_bfloat16* b = g_B + ((size_t)r * NB + row) * 128;
    for (int i = 0; i < 64; i++) {
        float v;
        if (row < 64) {
            v = Wr[row * 64 + i];
        } else {
            int h = (row - 64) & 7;
            int par = (row - 64) >> 3;     // 0 = even (s_in), 1 = odd (s_out)
            const float* q = query + ((size_t)r * HH + h) * 16 + par;
            float acc = 0.f;
            #pragma unroll
            for (int j = 0; j < 8; j++) acc += q[2 * j] * Wr[(h * 8 + j) * 64 + i];
            v = acc;
        }
        __nv_bfloat16 hi = __float2bfloat16(v);
        b[i]      = hi;
        b[64 + i] = __float2bfloat16(v - __bfloat162float(hi));
    }
}

// ---------------------------------------------------------------------------
// Kg: mma.sync bf16 GEMM, hi/lo cross terms, ldmatrix on BOTH operands.
//   CTA = 64 nodes x 80 cols, one relation.
//   Outer loop over B k16-chunks cb (0..7); 5x ldmatrix.x4 hoists all 10
//   n-tiles' B frags (20 regs); inner loop over paired A chunks:
//     cb<4:  ca = cb (hi*hi) and ca = cb+4 (lo*hi)
//     cb>=4: ca = cb-4 (hi*lo)            [lo*lo dropped, ~2^-18 rel]
// ---------------------------------------------------------------------------
__global__ __launch_bounds__(128) void k_gemm(int dummy) {
    __shared__ uint8_t sA[64 * 256];       // 16 KB, swizzled 16B chunks
    __shared__ uint8_t sB[NB * 256];       // 20 KB, same swizzle

    const int r     = blockIdx.y;
    const int mbase = blockIdx.x * 64;
    const int tid   = threadIdx.x;

    // ---- A: 64 rows x 256B; thread t loads half a row (8 uint4) ----
    {
        int row = tid >> 1, half = tid & 1;
        const uint4* src = (const uint4*)(g_xs + (size_t)(mbase + row) * 128) + half * 8;
        #pragma unroll
        for (int j = 0; j < 8; j++) {
            int chunk = half * 8 + j;
            *(uint4*)(sA + row * 256 + ((chunk ^ (row & 7)) << 4)) = src[j];
        }
    }
    // ---- B: 80 rows x 16 chunks, swizzled rows ----
    {
        const uint4* src = (const uint4*)(g_B + (size_t)r * NB * 128);
        #pragma unroll
        for (int j = 0; j < 10; j++) {
            int c = tid + j * 128;         // 0..1279
            int row = c >> 4, w = c & 15;
            *(uint4*)(sB + row * 256 + ((w ^ (row & 7)) << 4)) = src[c];
        }
    }
    __syncthreads();

    const int warp = tid >> 5, lane = tid & 31;
    const int g = lane >> 2, t = lane & 3;

    float acc[40];
    #pragma unroll
    for (int i = 0; i < 40; i++) acc[i] = 0.f;

    // A ldmatrix lane row / chunk-half selectors
    const int rowl = warp * 16 + ((lane >> 3) & 1) * 8 + (lane & 7);
    const int chsA = lane >> 4;
    // B ldmatrix lane row (within 16-row pair) / k-half selector
    const int bn   = ((lane >> 4) & 1) * 8 + (lane & 7);
    const int bks  = (lane >> 3) & 1;

    #pragma unroll
    for (int cb = 0; cb < 8; cb++) {
        // hoist B frags for all 10 n-tiles at chunk cb (pairs of tiles per x4)
        uint32_t bf[20];
        #pragma unroll
        for (int j = 0; j < 5; j++) {
            int n = j * 16 + bn;
            uint32_t addr = smem_u32(sB + n * 256 + (((2 * cb + bks) ^ (n & 7)) << 4));
            asm volatile("ldmatrix.sync.aligned.m8n8.x4.shared.b16 {%0,%1,%2,%3}, [%4];"
                         : "=r"(bf[4 * j]), "=r"(bf[4 * j + 1]),
                           "=r"(bf[4 * j + 2]), "=r"(bf[4 * j + 3]) : "r"(addr));
        }
        const int nA = (cb < 4) ? 2 : 1;
        #pragma unroll
        for (int u = 0; u < 2; u++) {
            if (u < nA) {
                const int ca = (u == 0) ? (cb & 3) : (cb + 4);
                uint32_t a0, a1, a2, a3;
                uint32_t addr = smem_u32(sA + rowl * 256 +
                                         (((2 * ca + chsA) ^ (rowl & 7)) << 4));
                asm volatile("ldmatrix.sync.aligned.m8n8.x4.shared.b16 {%0,%1,%2,%3}, [%4];"
                             : "=r"(a0), "=r"(a1), "=r"(a2), "=r"(a3) : "r"(addr));
                #pragma unroll
                for (int nt = 0; nt < 10; nt++) {
                    uint32_t b0 = bf[(nt >> 1) * 4 + (nt & 1) * 2];
                    uint32_t b1 = bf[(nt >> 1) * 4 + (nt & 1) * 2 + 1];
                    mma_bf16(acc + nt * 4, a0, a1, a2, a3, b0, b1);
                }
            }
        }
    }

    // ---- epilogue: direct STG.64 (rows g, g+8; col pairs nt*8+2t) ----
    #pragma unroll
    for (int half = 0; half < 2; half++) {
        int n = mbase + warp * 16 + g + 8 * half;
        if (n < NN) {
            float* hd = g_hidden + ((size_t)r * NN + n) * 64 + 2 * t;
            #pragma unroll
            for (int nt = 0; nt < 8; nt++)
                *(float2*)(hd + nt * 8) =
                    make_float2(acc[nt * 4 + 2 * half], acc[nt * 4 + 2 * half + 1]);
            float* sd = g_s + ((size_t)r * NN + n) * 16 + 2 * t;
            #pragma unroll
            for (int nt = 8; nt < 10; nt++)
                *(float2*)(sd + (nt - 8) * 8) =
                    make_float2(acc[nt * 4 + 2 * half], acc[nt * 4 + 2 * half + 1]);
        }
    }
}

// ---------------------------------------------------------------------------
// K2: fused edge attention + scatter. 8 threads/edge (one per head).
// ---------------------------------------------------------------------------
__device__ __forceinline__ void red_add_v4(float* p, float a, float b, float c, float d) {
    asm volatile("red.global.add.v4.f32 [%0], {%1,%2,%3,%4};"
                 :: "l"(p), "f"(a), "f"(b), "f"(c), "f"(d) : "memory");
}

__global__ __launch_bounds__(256) void k_edge(const int*   __restrict__ node_in,
                                              const int*   __restrict__ node_out,
                                              const int*   __restrict__ relation,
                                              const float* __restrict__ edge_weight) {
    const int t = blockIdx.x * 256 + threadIdx.x;
    const int m = t >> 3;
    const int h = t & 7;
    if (m >= MM) return;

    int ni, no, r; float ew;
    if (m < EE) {
        ni = node_in[m]; no = node_out[m]; r = relation[m]; ew = edge_weight[m];
    } else {
        ni = no = m - EE; r = RP1 - 1; ew = 1.f;
    }

    const size_t bi = (size_t)r * NN + ni;
    const size_t bo = (size_t)r * NN + no;
    float w = g_s[bi * 16 + h] + g_s[bo * 16 + 8 + h];
    w = (w > 0.f) ? w : NEG_SLOPE * w;
    float e = __expf(w) * ew;

    const float4* hin = (const float4*)(g_hidden + bi * 64 + h * 8);
    float4 a0 = hin[0], a1 = hin[1];

    float* um = g_um + (size_t)no * 64 + h * 8;
    red_add_v4(um,     e * a0.x, e * a0.y, e * a0.z, e * a0.w);
    red_add_v4(um + 4, e * a1.x, e * a1.y, e * a1.z, e * a1.w);
    atomicAdd(&g_sum[no * HH + h], e);
}

// ---------------------------------------------------------------------------
// K3: finalize: out = relu( um / sum )
//   (cnt*eps term <= 1.2e-8 relative — dropped; self-loop guarantees sum>0)
// ---------------------------------------------------------------------------
__global__ void k_final(float4* __restrict__ out) {
    int i = blockIdx.x * 256 + threadIdx.x;
    if (i >= NN * 16) return;
    int n = i >> 4;
    int h = (i & 15) >> 1;
    float inv = 1.f / g_sum[n * HH + h];
    float4 v = ((const float4*)g_um)[i];
    v.x *= inv; v.y *= inv; v.z *= inv; v.w *= inv;
    v.x = v.x > 0.f ? v.x : 0.f;
    v.y = v.y > 0.f ? v.y : 0.f;
    v.z = v.z > 0.f ? v.z : 0.f;
    v.w = v.w > 0.f ? v.w : 0.f;
    out[i] = v;
}

// ---------------------------------------------------------------------------
extern "C" void kernel_launch(void* const* d_in, const int* in_sizes, int n_in,
                              void* d_out, int out_size) {
    const float* x           = (const float*)d_in[0];
    const float* W_tau       = (const float*)d_in[1];
    const float* query       = (const float*)d_in[2];
    const int*   node_in     = (const int*)  d_in[3];
    const int*   node_out    = (const int*)  d_in[4];
    const int*   relation    = (const int*)  d_in[5];
    const float* edge_weight = (const float*)d_in[6];

    k_zero<<<(NN * 16 + 255) / 256, 256>>>();
    k_prepX<<<(NPAD * 8 + 255) / 256, 256>>>(x);
    k_prepW<<<RP1, NB>>>(W_tau, query);

    dim3 gg(MT, RP1);
    k_gemm<<<gg, 128>>>(0);

    k_edge<<<(MM * 8 + 255) / 256, 256>>>(node_in, node_out, relation, edge_weight);

    k_final<<<(NN * 16 + 255) / 256, 256>>>((float4*)d_out);
}

// round 6
// speedup vs baseline: 1.6113x; 1.1830x over previous
#include <cuda_runtime.h>
#include <cuda_bf16.h>
#include <cstdint>

// Problem constants
#define NN      50000        // nodes
#define EE      800000       // edges
#define MM      (EE + NN)    // edges + self loops
#define HH      8            // heads
#define RP1     9            // relations + 1 (self-loop relation = 8)
#define NEG_SLOPE 0.2f

#define NB      80           // GEMM N: 64 hidden dims + 8 s_in + 8 s_out
#define MT2     391          // ceil(NN / 128)
#define G16     3128         // ceil(NN/16) node-groups of 16 (padded: 391*8)

// ---------------------------------------------------------------------------
// Scratch (device globals; allocation-free per harness rules)
// ---------------------------------------------------------------------------
__device__ float          g_hidden[(size_t)RP1 * NN * 64];  // 115.2 MB
__device__ float          g_s[(size_t)RP1 * NN * 16];       // s_in[0..7] | s_out[8..15]
__device__ float          g_sum[NN * HH];
__device__ float          g_um[NN * 64];
__device__ __nv_bfloat16  g_B[RP1 * NB * 128];              // B' hi|lo rows (K=128)
__device__ uint4          g_xa[(size_t)G16 * 8 * 32];       // A in MMA-frag order
__device__ uint4          g_Bf[RP1 * 1280];                 // B in MMA-frag order

// ---------------------------------------------------------------------------
__device__ __forceinline__ void mma_bf16(float* c, uint32_t a0, uint32_t a1,
                                         uint32_t a2, uint32_t a3,
                                         uint32_t b0, uint32_t b1) {
    asm volatile(
        "mma.sync.aligned.m16n8k16.row.col.f32.bf16.bf16.f32 "
        "{%0,%1,%2,%3}, {%4,%5,%6,%7}, {%8,%9}, {%0,%1,%2,%3};"
        : "+f"(c[0]), "+f"(c[1]), "+f"(c[2]), "+f"(c[3])
        : "r"(a0), "r"(a1), "r"(a2), "r"(a3), "r"(b0), "r"(b1));
}

__device__ __forceinline__ uint32_t pack_bf2(float a, float b) {
    __nv_bfloat162 p = __halves2bfloat162(__float2bfloat16(a), __float2bfloat16(b));
    return *(uint32_t*)&p;
}
__device__ __forceinline__ float resid(float v) {
    return v - __bfloat162float(__float2bfloat16(v));
}

// ---------------------------------------------------------------------------
// K0: zero accumulators
// ---------------------------------------------------------------------------
__global__ void k_zero() {
    int i = blockIdx.x * 256 + threadIdx.x;
    if (i < NN * 16) ((float4*)g_um)[i]  = make_float4(0.f, 0.f, 0.f, 0.f);
    if (i < NN * 2)  ((float4*)g_sum)[i] = make_float4(0.f, 0.f, 0.f, 0.f);
}

// ---------------------------------------------------------------------------
// KpX: write x directly in m16n8k16 A-fragment order, bf16 hi|lo (K=128).
//   g_xa[g16][cb][lane] = uint4(a0,a1,a2,a3) for mtile g16, k16-chunk cb.
//   a0 = A[g][2t,2t+1], a1 = A[g+8][...], a2 = A[g][+8], a3 = A[g+8][+8].
//   Chunks 0..3 = x_hi cols 16cb.., chunks 4..7 = x_lo.
// ---------------------------------------------------------------------------
__global__ void k_prepX(const float* __restrict__ x) {
    int i = blockIdx.x * 256 + threadIdx.x;
    if (i >= G16 * 4 * 32) return;
    const int lane = i & 31;
    const int cbb  = (i >> 5) & 3;
    const int g16  = i >> 7;
    const int g = lane >> 2, t = lane & 3;
    const int n0 = g16 * 16 + g, n1 = n0 + 8;
    const int c0 = cbb * 16 + 2 * t;

    float2 v00 = {0.f, 0.f}, v01 = {0.f, 0.f}, v10 = {0.f, 0.f}, v11 = {0.f, 0.f};
    if (n0 < NN) {
        v00 = *(const float2*)(x + (size_t)n0 * 64 + c0);
        v01 = *(const float2*)(x + (size_t)n0 * 64 + c0 + 8);
    }
    if (n1 < NN) {
        v10 = *(const float2*)(x + (size_t)n1 * 64 + c0);
        v11 = *(const float2*)(x + (size_t)n1 * 64 + c0 + 8);
    }
    uint4 hi, lo;
    hi.x = pack_bf2(v00.x, v00.y);         lo.x = pack_bf2(resid(v00.x), resid(v00.y));
    hi.y = pack_bf2(v10.x, v10.y);         lo.y = pack_bf2(resid(v10.x), resid(v10.y));
    hi.z = pack_bf2(v01.x, v01.y);         lo.z = pack_bf2(resid(v01.x), resid(v01.y));
    hi.w = pack_bf2(v11.x, v11.y);         lo.w = pack_bf2(resid(v11.x), resid(v11.y));

    g_xa[((size_t)g16 * 8 + cbb) * 32 + lane]     = hi;
    g_xa[((size_t)g16 * 8 + cbb + 4) * 32 + lane] = lo;
}

// ---------------------------------------------------------------------------
// KpWB: phase 1 — B' rows = [W_tau | q_even-folded | q_odd-folded], bf16
//   hi|lo K=128 into g_B. phase 2 — permute to B-fragment order g_Bf:
//   g_Bf[r][cb][j][lane] = (b0 nt=2j, b1 nt=2j, b0 nt=2j+1, b1 nt=2j+1),
//   b0(nt) lane l = B[nt*8 + (l>>2)][16cb + 2(l&3) .. +1], b1 = k+8.
// ---------------------------------------------------------------------------
__global__ void k_prepWB(const float* __restrict__ W, const float* __restrict__ query) {
    const int r = blockIdx.x, tid = threadIdx.x;
    const float* Wr = W + (size_t)r * 64 * 64;

    if (tid < NB) {
        __nv_bfloat16* b = g_B + ((size_t)r * NB + tid) * 128;
        for (int i = 0; i < 64; i++) {
            float v;
            if (tid < 64) {
                v = Wr[tid * 64 + i];
            } else {
                int h = (tid - 64) & 7;
                int par = (tid - 64) >> 3;
                const float* q = query + ((size_t)r * HH + h) * 16 + par;
                float acc = 0.f;
                #pragma unroll
                for (int j = 0; j < 8; j++) acc += q[2 * j] * Wr[(h * 8 + j) * 64 + i];
                v = acc;
            }
            __nv_bfloat16 hi = __float2bfloat16(v);
            b[i]      = hi;
            b[64 + i] = __float2bfloat16(v - __bfloat162float(hi));
        }
    }
    __syncthreads();

    #pragma unroll
    for (int k = 0; k < 5; k++) {
        int f = tid + k * 256;             // 0..1279
        int cb   = f / 160;
        int rem  = f - cb * 160;
        int j    = rem >> 5;
        int lane = rem & 31;
        int g = lane >> 2, t = lane & 3;
        const __nv_bfloat16* B0 = g_B + ((size_t)r * NB + j * 16 + g) * 128;
        const __nv_bfloat16* B1 = B0 + 8 * 128;
        uint4 v;
        v.x = *(const uint32_t*)(B0 + cb * 16 + 2 * t);
        v.y = *(const uint32_t*)(B0 + cb * 16 + 8 + 2 * t);
        v.z = *(const uint32_t*)(B1 + cb * 16 + 2 * t);
        v.w = *(const uint32_t*)(B1 + cb * 16 + 8 + 2 * t);
        g_Bf[r * 1280 + f] = v;
    }
}

// ---------------------------------------------------------------------------
// Kg: mma.sync bf16 GEMM, frag-direct A (no smem, no ldmatrix).
//   CTA = 128 nodes x 80 cols for one relation; 4 warps x m32 each.
//   A frags: 16 coalesced LDG.128 per thread. B frags: smem stage once,
//   LDS.128 per (cb, ntile-pair). hi/lo pairing:
//     cb<4 (w_hi): ca = cb (hi*hi), ca = cb+4 (lo*hi)
//     cb>=4 (w_lo): ca = cb-4 (hi*lo)    [lo*lo dropped, ~2^-18 rel]
// ---------------------------------------------------------------------------
__global__ __launch_bounds__(128) void k_gemm(int dummy) {
    __shared__ uint4 sBf[1280];            // 20 KB

    const int r     = blockIdx.y;
    const int mbase = blockIdx.x * 128;
    const int tid   = threadIdx.x;
    const int w     = tid >> 5, lane = tid & 31;

    // stage B frags (coalesced)
    #pragma unroll
    for (int k = 0; k < 10; k++)
        sBf[tid + k * 128] = g_Bf[r * 1280 + tid + k * 128];

    // A frags straight to registers
    uint4 af[2][8];
    const int gb = blockIdx.x * 8 + w * 2;
    #pragma unroll
    for (int i = 0; i < 2; i++)
        #pragma unroll
        for (int cb = 0; cb < 8; cb++)
            af[i][cb] = g_xa[((size_t)(gb + i) * 8 + cb) * 32 + lane];

    __syncthreads();

    float acc[2][40];
    #pragma unroll
    for (int i = 0; i < 2; i++)
        #pragma unroll
        for (int k = 0; k < 40; k++) acc[i][k] = 0.f;

    #pragma unroll
    for (int cb = 0; cb < 8; cb++) {
        uint4 bf[5];
        #pragma unroll
        for (int j = 0; j < 5; j++) bf[j] = sBf[(cb * 5 + j) * 32 + lane];

        const int nA = (cb < 4) ? 2 : 1;
        #pragma unroll
        for (int u = 0; u < 2; u++) {
            if (u < nA) {
                const int ca = (u == 0) ? ((cb < 4) ? cb : cb - 4) : cb + 4;
                #pragma unroll
                for (int i = 0; i < 2; i++)
                    #pragma unroll
                    for (int nt = 0; nt < 10; nt++) {
                        uint32_t b0 = (nt & 1) ? bf[nt >> 1].z : bf[nt >> 1].x;
                        uint32_t b1 = (nt & 1) ? bf[nt >> 1].w : bf[nt >> 1].y;
                        mma_bf16(acc[i] + nt * 4, af[i][ca].x, af[i][ca].y,
                                 af[i][ca].z, af[i][ca].w, b0, b1);
                    }
            }
        }
    }

    // ---- epilogue: direct STG.64 ----
    const int g = lane >> 2, t = lane & 3;
    #pragma unroll
    for (int i = 0; i < 2; i++)
        #pragma unroll
        for (int half = 0; half < 2; half++) {
            int n = mbase + w * 32 + i * 16 + g + 8 * half;
            if (n < NN) {
                float* hd = g_hidden + ((size_t)r * NN + n) * 64 + 2 * t;
                #pragma unroll
                for (int nt = 0; nt < 8; nt++)
                    *(float2*)(hd + nt * 8) =
                        make_float2(acc[i][nt * 4 + 2 * half], acc[i][nt * 4 + 2 * half + 1]);
                float* sd = g_s + ((size_t)r * NN + n) * 16 + 2 * t;
                #pragma unroll
                for (int nt = 8; nt < 10; nt++)
                    *(float2*)(sd + (nt - 8) * 8) =
                        make_float2(acc[i][nt * 4 + 2 * half], acc[i][nt * 4 + 2 * half + 1]);
            }
        }
}

// ---------------------------------------------------------------------------
// K2: fused edge attention + scatter. 8 threads/edge (one per head).
//   g_sum scatter coalesced to 2x red.v4 per edge via quad shuffles.
// ---------------------------------------------------------------------------
__device__ __forceinline__ void red_add_v4(float* p, float a, float b, float c, float d) {
    asm volatile("red.global.add.v4.f32 [%0], {%1,%2,%3,%4};"
                 :: "l"(p), "f"(a), "f"(b), "f"(c), "f"(d) : "memory");
}

__global__ __launch_bounds__(256) void k_edge(const int*   __restrict__ node_in,
                                              const int*   __restrict__ node_out,
                                              const int*   __restrict__ relation,
                                              const float* __restrict__ edge_weight) {
    const int tt = blockIdx.x * 256 + threadIdx.x;
    int m = tt >> 3;
    const int h = tt & 7;
    const bool act = (m < MM);
    if (!act) m = MM - 1;                  // clamp; stores guarded below

    int ni, no, r; float ew;
    if (m < EE) {
        ni = node_in[m]; no = node_out[m]; r = relation[m]; ew = edge_weight[m];
    } else {
        ni = no = m - EE; r = RP1 - 1; ew = 1.f;
    }

    const size_t bi = (size_t)r * NN + ni;
    const size_t bo = (size_t)r * NN + no;
    float w = g_s[bi * 16 + h] + g_s[bo * 16 + 8 + h];
    w = (w > 0.f) ? w : NEG_SLOPE * w;
    float e = __expf(w) * ew;

    // gather quad e's (octet-local; all lanes participate)
    float e1 = __shfl_down_sync(0xffffffffu, e, 1);
    float e2 = __shfl_down_sync(0xffffffffu, e, 2);
    float e3 = __shfl_down_sync(0xffffffffu, e, 3);

    if (act) {
        const float4* hin = (const float4*)(g_hidden + bi * 64 + h * 8);
        float4 a0 = hin[0], a1 = hin[1];

        float* um = g_um + (size_t)no * 64 + h * 8;
        red_add_v4(um,     e * a0.x, e * a0.y, e * a0.z, e * a0.w);
        red_add_v4(um + 4, e * a1.x, e * a1.y, e * a1.z, e * a1.w);
        if ((h & 3) == 0)
            red_add_v4(&g_sum[no * HH + h], e, e1, e2, e3);
    }
}

// ---------------------------------------------------------------------------
// K3: finalize: out = relu( um / sum )
//   (cnt*eps term <= 1.2e-8 relative — dropped; self-loop guarantees sum>0)
// ---------------------------------------------------------------------------
__global__ void k_final(float4* __restrict__ out) {
    int i = blockIdx.x * 256 + threadIdx.x;
    if (i >= NN * 16) return;
    int n = i >> 4;
    int h = (i & 15) >> 1;
    float inv = 1.f / g_sum[n * HH + h];
    float4 v = ((const float4*)g_um)[i];
    v.x *= inv; v.y *= inv; v.z *= inv; v.w *= inv;
    v.x = v.x > 0.f ? v.x : 0.f;
    v.y = v.y > 0.f ? v.y : 0.f;
    v.z = v.z > 0.f ? v.z : 0.f;
    v.w = v.w > 0.f ? v.w : 0.f;
    out[i] = v;
}

// ---------------------------------------------------------------------------
extern "C" void kernel_launch(void* const* d_in, const int* in_sizes, int n_in,
                              void* d_out, int out_size) {
    const float* x           = (const float*)d_in[0];
    const float* W_tau       = (const float*)d_in[1];
    const float* query       = (const float*)d_in[2];
    const int*   node_in     = (const int*)  d_in[3];
    const int*   node_out    = (const int*)  d_in[4];
    const int*   relation    = (const int*)  d_in[5];
    const float* edge_weight = (const float*)d_in[6];

    k_zero<<<(NN * 16 + 255) / 256, 256>>>();
    k_prepX<<<(G16 * 4 * 32 + 255) / 256, 256>>>(x);
    k_prepWB<<<RP1, 256>>>(W_tau, query);

    dim3 gg(MT2, RP1);
    k_gemm<<<gg, 128>>>(0);

    k_edge<<<((MM * 8) + 255) / 256, 256>>>(node_in, node_out, relation, edge_weight);

    k_final<<<(NN * 16 + 255) / 256, 256>>>((float4*)d_out);
}

// round 7
// speedup vs baseline: 1.7239x; 1.0699x over previous
#include <cuda_runtime.h>
#include <cuda_bf16.h>
#include <cuda_fp16.h>
#include <cstdint>

// Problem constants
#define NN      50000        // nodes
#define EE      800000       // edges
#define MM      (EE + NN)    // edges + self loops
#define HH      8            // heads
#define RP1     9            // relations + 1 (self-loop relation = 8)
#define NEG_SLOPE 0.2f

#define NB      80           // GEMM N: 64 hidden dims + 8 s_in + 8 s_out
#define MT2     391          // ceil(NN / 128)
#define G16     3128         // 391*8 node-groups of 16

// ---------------------------------------------------------------------------
// Scratch (device globals; allocation-free per harness rules)
// ---------------------------------------------------------------------------
__device__ __half         g_hidden[(size_t)RP1 * NN * 64]; // 57.6 MB (fp16!)
__device__ __half         g_s[(size_t)RP1 * NN * 16];      // 14.4 MB (fp16!)
__device__ float          g_sum[NN * HH];
__device__ float          g_um[NN * 64];
__device__ __nv_bfloat16  g_B[RP1 * NB * 128];             // B' hi|lo rows (K=128)
__device__ uint4          g_xa[(size_t)G16 * 8 * 32];      // A in MMA-frag order
__device__ uint4          g_Bf[RP1 * 1280];                // B in MMA-frag order

// ---------------------------------------------------------------------------
__device__ __forceinline__ void mma_bf16(float* c, uint32_t a0, uint32_t a1,
                                         uint32_t a2, uint32_t a3,
                                         uint32_t b0, uint32_t b1) {
    asm volatile(
        "mma.sync.aligned.m16n8k16.row.col.f32.bf16.bf16.f32 "
        "{%0,%1,%2,%3}, {%4,%5,%6,%7}, {%8,%9}, {%0,%1,%2,%3};"
        : "+f"(c[0]), "+f"(c[1]), "+f"(c[2]), "+f"(c[3])
        : "r"(a0), "r"(a1), "r"(a2), "r"(a3), "r"(b0), "r"(b1));
}

__device__ __forceinline__ uint32_t pack_bf2(float a, float b) {
    __nv_bfloat162 p = __halves2bfloat162(__float2bfloat16(a), __float2bfloat16(b));
    return *(uint32_t*)&p;
}
__device__ __forceinline__ float resid(float v) {
    return v - __bfloat162float(__float2bfloat16(v));
}
__device__ __forceinline__ uint32_t pack_h2(float a, float b) {
    __half2 p = __floats2half2_rn(a, b);
    return *(uint32_t*)&p;
}

// ---------------------------------------------------------------------------
// K0: zero accumulators
// ---------------------------------------------------------------------------
__global__ void k_zero() {
    int i = blockIdx.x * 256 + threadIdx.x;
    if (i < NN * 16) ((float4*)g_um)[i]  = make_float4(0.f, 0.f, 0.f, 0.f);
    if (i < NN * 2)  ((float4*)g_sum)[i] = make_float4(0.f, 0.f, 0.f, 0.f);
}

// ---------------------------------------------------------------------------
// KpX: write x directly in m16n8k16 A-fragment order, bf16 hi|lo (K=128).
// ---------------------------------------------------------------------------
__global__ void k_prepX(const float* __restrict__ x) {
    int i = blockIdx.x * 256 + threadIdx.x;
    if (i >= G16 * 4 * 32) return;
    const int lane = i & 31;
    const int cbb  = (i >> 5) & 3;
    const int g16  = i >> 7;
    const int g = lane >> 2, t = lane & 3;
    const int n0 = g16 * 16 + g, n1 = n0 + 8;
    const int c0 = cbb * 16 + 2 * t;

    float2 v00 = {0.f, 0.f}, v01 = {0.f, 0.f}, v10 = {0.f, 0.f}, v11 = {0.f, 0.f};
    if (n0 < NN) {
        v00 = *(const float2*)(x + (size_t)n0 * 64 + c0);
        v01 = *(const float2*)(x + (size_t)n0 * 64 + c0 + 8);
    }
    if (n1 < NN) {
        v10 = *(const float2*)(x + (size_t)n1 * 64 + c0);
        v11 = *(const float2*)(x + (size_t)n1 * 64 + c0 + 8);
    }
    uint4 hi, lo;
    hi.x = pack_bf2(v00.x, v00.y);         lo.x = pack_bf2(resid(v00.x), resid(v00.y));
    hi.y = pack_bf2(v10.x, v10.y);         lo.y = pack_bf2(resid(v10.x), resid(v10.y));
    hi.z = pack_bf2(v01.x, v01.y);         lo.z = pack_bf2(resid(v01.x), resid(v01.y));
    hi.w = pack_bf2(v11.x, v11.y);         lo.w = pack_bf2(resid(v11.x), resid(v11.y));

    g_xa[((size_t)g16 * 8 + cbb) * 32 + lane]     = hi;
    g_xa[((size_t)g16 * 8 + cbb + 4) * 32 + lane] = lo;
}

// ---------------------------------------------------------------------------
// KpWB: B' rows = [W_tau | q_even-folded | q_odd-folded], bf16 hi|lo, then
//   permute to B-fragment order in g_Bf.
// ---------------------------------------------------------------------------
__global__ void k_prepWB(const float* __restrict__ W, const float* __restrict__ query) {
    const int r = blockIdx.x, tid = threadIdx.x;
    const float* Wr = W + (size_t)r * 64 * 64;

    if (tid < NB) {
        __nv_bfloat16* b = g_B + ((size_t)r * NB + tid) * 128;
        for (int i = 0; i < 64; i++) {
            float v;
            if (tid < 64) {
                v = Wr[tid * 64 + i];
            } else {
                int h = (tid - 64) & 7;
                int par = (tid - 64) >> 3;
                const float* q = query + ((size_t)r * HH + h) * 16 + par;
                float acc = 0.f;
                #pragma unroll
                for (int j = 0; j < 8; j++) acc += q[2 * j] * Wr[(h * 8 + j) * 64 + i];
                v = acc;
            }
            __nv_bfloat16 hi = __float2bfloat16(v);
            b[i]      = hi;
            b[64 + i] = __float2bfloat16(v - __bfloat162float(hi));
        }
    }
    __syncthreads();

    #pragma unroll
    for (int k = 0; k < 5; k++) {
        int f = tid + k * 256;             // 0..1279
        int cb   = f / 160;
        int rem  = f - cb * 160;
        int j    = rem >> 5;
        int lane = rem & 31;
        int g = lane >> 2, t = lane & 3;
        const __nv_bfloat16* B0 = g_B + ((size_t)r * NB + j * 16 + g) * 128;
        const __nv_bfloat16* B1 = B0 + 8 * 128;
        uint4 v;
        v.x = *(const uint32_t*)(B0 + cb * 16 + 2 * t);
        v.y = *(const uint32_t*)(B0 + cb * 16 + 8 + 2 * t);
        v.z = *(const uint32_t*)(B1 + cb * 16 + 2 * t);
        v.w = *(const uint32_t*)(B1 + cb * 16 + 8 + 2 * t);
        g_Bf[r * 1280 + f] = v;
    }
}

// ---------------------------------------------------------------------------
// Kg: mma.sync bf16 GEMM, frag-direct A. CTA = 128 nodes x 80 cols.
//   Epilogue converts to fp16 (half2 STG.32) — halves store traffic.
// ---------------------------------------------------------------------------
__global__ __launch_bounds__(128) void k_gemm(int dummy) {
    __shared__ uint4 sBf[1280];            // 20 KB

    const int r     = blockIdx.y;
    const int mbase = blockIdx.x * 128;
    const int tid   = threadIdx.x;
    const int w     = tid >> 5, lane = tid & 31;

    #pragma unroll
    for (int k = 0; k < 10; k++)
        sBf[tid + k * 128] = g_Bf[r * 1280 + tid + k * 128];

    uint4 af[2][8];
    const int gb = blockIdx.x * 8 + w * 2;
    #pragma unroll
    for (int i = 0; i < 2; i++)
        #pragma unroll
        for (int cb = 0; cb < 8; cb++)
            af[i][cb] = g_xa[((size_t)(gb + i) * 8 + cb) * 32 + lane];

    __syncthreads();

    float acc[2][40];
    #pragma unroll
    for (int i = 0; i < 2; i++)
        #pragma unroll
        for (int k = 0; k < 40; k++) acc[i][k] = 0.f;

    #pragma unroll
    for (int cb = 0; cb < 8; cb++) {
        uint4 bf[5];
        #pragma unroll
        for (int j = 0; j < 5; j++) bf[j] = sBf[(cb * 5 + j) * 32 + lane];

        const int nA = (cb < 4) ? 2 : 1;
        #pragma unroll
        for (int u = 0; u < 2; u++) {
            if (u < nA) {
                const int ca = (u == 0) ? ((cb < 4) ? cb : cb - 4) : cb + 4;
                #pragma unroll
                for (int i = 0; i < 2; i++)
                    #pragma unroll
                    for (int nt = 0; nt < 10; nt++) {
                        uint32_t b0 = (nt & 1) ? bf[nt >> 1].z : bf[nt >> 1].x;
                        uint32_t b1 = (nt & 1) ? bf[nt >> 1].w : bf[nt >> 1].y;
                        mma_bf16(acc[i] + nt * 4, af[i][ca].x, af[i][ca].y,
                                 af[i][ca].z, af[i][ca].w, b0, b1);
                    }
            }
        }
    }

    // ---- epilogue: fp16 half2 stores ----
    const int g = lane >> 2, t = lane & 3;
    #pragma unroll
    for (int i = 0; i < 2; i++)
        #pragma unroll
        for (int half = 0; half < 2; half++) {
            int n = mbase + w * 32 + i * 16 + g + 8 * half;
            if (n < NN) {
                uint32_t* hd = (uint32_t*)(g_hidden + ((size_t)r * NN + n) * 64 + 2 * t);
                #pragma unroll
                for (int nt = 0; nt < 8; nt++)
                    hd[nt * 4] = pack_h2(acc[i][nt * 4 + 2 * half],
                                         acc[i][nt * 4 + 2 * half + 1]);
                uint32_t* sd = (uint32_t*)(g_s + ((size_t)r * NN + n) * 16 + 2 * t);
                #pragma unroll
                for (int nt = 8; nt < 10; nt++)
                    sd[(nt - 8) * 4] = pack_h2(acc[i][nt * 4 + 2 * half],
                                               acc[i][nt * 4 + 2 * half + 1]);
            }
        }
}

// ---------------------------------------------------------------------------
// K2: fused edge attention + scatter. 8 threads/edge (one per head).
//   fp16 gathers (1 cache line h_in per edge); fp32 accumulators.
// ---------------------------------------------------------------------------
__device__ __forceinline__ void red_add_v4(float* p, float a, float b, float c, float d) {
    asm volatile("red.global.add.v4.f32 [%0], {%1,%2,%3,%4};"
                 :: "l"(p), "f"(a), "f"(b), "f"(c), "f"(d) : "memory");
}

__global__ __launch_bounds__(256) void k_edge(const int*   __restrict__ node_in,
                                              const int*   __restrict__ node_out,
                                              const int*   __restrict__ relation,
                                              const float* __restrict__ edge_weight) {
    const int tt = blockIdx.x * 256 + threadIdx.x;
    int m = tt >> 3;
    const int h = tt & 7;
    const bool act = (m < MM);
    if (!act) m = MM - 1;                  // clamp; stores guarded below

    int ni, no, r; float ew;
    if (m < EE) {
        ni = node_in[m]; no = node_out[m]; r = relation[m]; ew = edge_weight[m];
    } else {
        ni = no = m - EE; r = RP1 - 1; ew = 1.f;
    }

    const size_t bi = (size_t)r * NN + ni;
    const size_t bo = (size_t)r * NN + no;
    float w = __half2float(g_s[bi * 16 + h]) + __half2float(g_s[bo * 16 + 8 + h]);
    w = (w > 0.f) ? w : NEG_SLOPE * w;
    float e = __expf(w) * ew;

    // gather quad e's (octet-local; all lanes participate)
    float e1 = __shfl_down_sync(0xffffffffu, e, 1);
    float e2 = __shfl_down_sync(0xffffffffu, e, 2);
    float e3 = __shfl_down_sync(0xffffffffu, e, 3);

    if (act) {
        uint4 hv = *(const uint4*)(g_hidden + bi * 64 + h * 8);
        float2 f0 = __half22float2(*(__half2*)&hv.x);
        float2 f1 = __half22float2(*(__half2*)&hv.y);
        float2 f2 = __half22float2(*(__half2*)&hv.z);
        float2 f3 = __half22float2(*(__half2*)&hv.w);

        float* um = g_um + (size_t)no * 64 + h * 8;
        red_add_v4(um,     e * f0.x, e * f0.y, e * f1.x, e * f1.y);
        red_add_v4(um + 4, e * f2.x, e * f2.y, e * f3.x, e * f3.y);
        if ((h & 3) == 0)
            red_add_v4(&g_sum[no * HH + h], e, e1, e2, e3);
    }
}

// ---------------------------------------------------------------------------
// K3: finalize: out = relu( um / sum )
// ---------------------------------------------------------------------------
__global__ void k_final(float4* __restrict__ out) {
    int i = blockIdx.x * 256 + threadIdx.x;
    if (i >= NN * 16) return;
    int n = i >> 4;
    int h = (i & 15) >> 1;
    float inv = 1.f / g_sum[n * HH + h];
    float4 v = ((const float4*)g_um)[i];
    v.x *= inv; v.y *= inv; v.z *= inv; v.w *= inv;
    v.x = v.x > 0.f ? v.x : 0.f;
    v.y = v.y > 0.f ? v.y : 0.f;
    v.z = v.z > 0.f ? v.z : 0.f;
    v.w = v.w > 0.f ? v.w : 0.f;
    out[i] = v;
}

// ---------------------------------------------------------------------------
extern "C" void kernel_launch(void* const* d_in, const int* in_sizes, int n_in,
                              void* d_out, int out_size) {
    const float* x           = (const float*)d_in[0];
    const float* W_tau       = (const float*)d_in[1];
    const float* query       = (const float*)d_in[2];
    const int*   node_in     = (const int*)  d_in[3];
    const int*   node_out    = (const int*)  d_in[4];
    const int*   relation    = (const int*)  d_in[5];
    const float* edge_weight = (const float*)d_in[6];

    k_zero<<<(NN * 16 + 255) / 256, 256>>>();
    k_prepX<<<(G16 * 4 * 32 + 255) / 256, 256>>>(x);
    k_prepWB<<<RP1, 256>>>(W_tau, query);

    dim3 gg(MT2, RP1);
    k_gemm<<<gg, 128>>>(0);

    k_edge<<<((MM * 8) + 255) / 256, 256>>>(node_in, node_out, relation, edge_weight);

    k_final<<<(NN * 16 + 255) / 256, 256>>>((float4*)d_out);
}

// round 8
// speedup vs baseline: 1.7685x; 1.0259x over previous
#include <cuda_runtime.h>
#include <cuda_bf16.h>
#include <cuda_fp16.h>
#include <cstdint>

// Problem constants
#define NN      50000        // nodes
#define EE      800000       // edges
#define MM      (EE + NN)    // edges + self loops
#define HH      8            // heads
#define RP1     9            // relations + 1 (self-loop relation = 8)
#define NEG_SLOPE 0.2f

#define NB      80           // GEMM N: 64 hidden dims + 8 s_in + 8 s_out
#define MT2     391          // ceil(NN / 128)
#define G16     3128         // 391*8 node-groups of 16
#define SB1     196          // ceil(NN / 256) scan blocks

// ---------------------------------------------------------------------------
// Scratch (device globals; allocation-free per harness rules)
// ---------------------------------------------------------------------------
__device__ __half         g_hidden[(size_t)RP1 * NN * 64]; // 57.6 MB fp16
__device__ __half         g_s[(size_t)RP1 * NN * 16];      // 14.4 MB fp16
__device__ __nv_bfloat16  g_B[RP1 * NB * 128];             // B' hi|lo rows (K=128)
__device__ uint4          g_xa[(size_t)G16 * 8 * 32];      // A in MMA-frag order
__device__ uint4          g_Bf[RP1 * 1280];                // B in MMA-frag order
// CSR sort scratch
__device__ int            g_cnt[NN];
__device__ int            g_cnt2[NN];
__device__ int            g_off[NN + 1];
__device__ int            g_bsum[256];
__device__ uint2          g_erec[MM];                      // (ni | rel<<16, ew)

// ---------------------------------------------------------------------------
__device__ __forceinline__ void mma_bf16(float* c, uint32_t a0, uint32_t a1,
                                         uint32_t a2, uint32_t a3,
                                         uint32_t b0, uint32_t b1) {
    asm volatile(
        "mma.sync.aligned.m16n8k16.row.col.f32.bf16.bf16.f32 "
        "{%0,%1,%2,%3}, {%4,%5,%6,%7}, {%8,%9}, {%0,%1,%2,%3};"
        : "+f"(c[0]), "+f"(c[1]), "+f"(c[2]), "+f"(c[3])
        : "r"(a0), "r"(a1), "r"(a2), "r"(a3), "r"(b0), "r"(b1));
}
__device__ __forceinline__ uint32_t pack_bf2(float a, float b) {
    __nv_bfloat162 p = __halves2bfloat162(__float2bfloat16(a), __float2bfloat16(b));
    return *(uint32_t*)&p;
}
__device__ __forceinline__ float resid(float v) {
    return v - __bfloat162float(__float2bfloat16(v));
}
__device__ __forceinline__ uint32_t pack_h2(float a, float b) {
    __half2 p = __floats2half2_rn(a, b);
    return *(uint32_t*)&p;
}

// ---------------------------------------------------------------------------
// K0: zero sort counters
// ---------------------------------------------------------------------------
__global__ void k_zero() {
    int i = blockIdx.x * 256 + threadIdx.x;
    if (i < NN) { g_cnt[i] = 0; g_cnt2[i] = 0; }
}

// ---------------------------------------------------------------------------
// KpX: write x directly in m16n8k16 A-fragment order, bf16 hi|lo (K=128).
// ---------------------------------------------------------------------------
__global__ void k_prepX(const float* __restrict__ x) {
    int i = blockIdx.x * 256 + threadIdx.x;
    if (i >= G16 * 4 * 32) return;
    const int lane = i & 31;
    const int cbb  = (i >> 5) & 3;
    const int g16  = i >> 7;
    const int g = lane >> 2, t = lane & 3;
    const int n0 = g16 * 16 + g, n1 = n0 + 8;
    const int c0 = cbb * 16 + 2 * t;

    float2 v00 = {0.f, 0.f}, v01 = {0.f, 0.f}, v10 = {0.f, 0.f}, v11 = {0.f, 0.f};
    if (n0 < NN) {
        v00 = *(const float2*)(x + (size_t)n0 * 64 + c0);
        v01 = *(const float2*)(x + (size_t)n0 * 64 + c0 + 8);
    }
    if (n1 < NN) {
        v10 = *(const float2*)(x + (size_t)n1 * 64 + c0);
        v11 = *(const float2*)(x + (size_t)n1 * 64 + c0 + 8);
    }
    uint4 hi, lo;
    hi.x = pack_bf2(v00.x, v00.y);         lo.x = pack_bf2(resid(v00.x), resid(v00.y));
    hi.y = pack_bf2(v10.x, v10.y);         lo.y = pack_bf2(resid(v10.x), resid(v10.y));
    hi.z = pack_bf2(v01.x, v01.y);         lo.z = pack_bf2(resid(v01.x), resid(v01.y));
    hi.w = pack_bf2(v11.x, v11.y);         lo.w = pack_bf2(resid(v11.x), resid(v11.y));

    g_xa[((size_t)g16 * 8 + cbb) * 32 + lane]     = hi;
    g_xa[((size_t)g16 * 8 + cbb + 4) * 32 + lane] = lo;
}

// ---------------------------------------------------------------------------
// KpWB: B' rows = [W_tau | q_even-folded | q_odd-folded], bf16 hi|lo, then
//   permute to B-fragment order in g_Bf.
// ---------------------------------------------------------------------------
__global__ void k_prepWB(const float* __restrict__ W, const float* __restrict__ query) {
    const int r = blockIdx.x, tid = threadIdx.x;
    const float* Wr = W + (size_t)r * 64 * 64;

    if (tid < NB) {
        __nv_bfloat16* b = g_B + ((size_t)r * NB + tid) * 128;
        for (int i = 0; i < 64; i++) {
            float v;
            if (tid < 64) {
                v = Wr[tid * 64 + i];
            } else {
                int h = (tid - 64) & 7;
                int par = (tid - 64) >> 3;
                const float* q = query + ((size_t)r * HH + h) * 16 + par;
                float acc = 0.f;
                #pragma unroll
                for (int j = 0; j < 8; j++) acc += q[2 * j] * Wr[(h * 8 + j) * 64 + i];
                v = acc;
            }
            __nv_bfloat16 hi = __float2bfloat16(v);
            b[i]      = hi;
            b[64 + i] = __float2bfloat16(v - __bfloat162float(hi));
        }
    }
    __syncthreads();

    #pragma unroll
    for (int k = 0; k < 5; k++) {
        int f = tid + k * 256;             // 0..1279
        int cb   = f / 160;
        int rem  = f - cb * 160;
        int j    = rem >> 5;
        int lane = rem & 31;
        int g = lane >> 2, t = lane & 3;
        const __nv_bfloat16* B0 = g_B + ((size_t)r * NB + j * 16 + g) * 128;
        const __nv_bfloat16* B1 = B0 + 8 * 128;
        uint4 v;
        v.x = *(const uint32_t*)(B0 + cb * 16 + 2 * t);
        v.y = *(const uint32_t*)(B0 + cb * 16 + 8 + 2 * t);
        v.z = *(const uint32_t*)(B1 + cb * 16 + 2 * t);
        v.w = *(const uint32_t*)(B1 + cb * 16 + 8 + 2 * t);
        g_Bf[r * 1280 + f] = v;
    }
}

// ---------------------------------------------------------------------------
// Counting sort by destination: histogram -> 2-level scan -> scatter
// ---------------------------------------------------------------------------
__global__ void k_hist(const int* __restrict__ node_out) {
    int m = blockIdx.x * 256 + threadIdx.x;
    if (m >= MM) return;
    int no = (m < EE) ? node_out[m] : (m - EE);
    atomicAdd(&g_cnt[no], 1);
}

__device__ __forceinline__ int block_incl_scan(int v, int* wt) {
    int lane = threadIdx.x & 31, w = threadIdx.x >> 5;
    #pragma unroll
    for (int o = 1; o < 32; o <<= 1) {
        int y = __shfl_up_sync(0xffffffffu, v, o);
        if (lane >= o) v += y;
    }
    if (lane == 31) wt[w] = v;
    __syncthreads();
    if (w == 0) {
        int x = (lane < 8) ? wt[lane] : 0;
        #pragma unroll
        for (int o = 1; o < 8; o <<= 1) {
            int y = __shfl_up_sync(0xffffffffu, x, o);
            if (lane >= o) x += y;
        }
        if (lane < 8) wt[lane] = x;
    }
    __syncthreads();
    return v + ((w > 0) ? wt[w - 1] : 0);
}

__global__ void k_scan1() {
    __shared__ int wt[8];
    int i = blockIdx.x * 256 + threadIdx.x;
    int v0 = (i < NN) ? g_cnt[i] : 0;
    int incl = block_incl_scan(v0, wt);
    if (i < NN) g_off[i] = incl - v0;      // block-local exclusive
    if (threadIdx.x == 255) g_bsum[blockIdx.x] = incl;
}

__global__ void k_scan2() {
    __shared__ int wt[8];
    int i = threadIdx.x;
    int v0 = (i < SB1) ? g_bsum[i] : 0;
    int incl = block_incl_scan(v0, wt);
    g_bsum[i] = incl - v0;                 // exclusive block offsets
}

__global__ void k_scan3() {
    int i = blockIdx.x * 256 + threadIdx.x;
    if (i < NN) g_off[i] += g_bsum[i >> 8];
    if (i == 0) g_off[NN] = MM;
}

__global__ void k_scatter(const int* __restrict__ node_in,
                          const int* __restrict__ node_out,
                          const int* __restrict__ relation,
                          const float* __restrict__ edge_weight) {
    int m = blockIdx.x * 256 + threadIdx.x;
    if (m >= MM) return;
    int ni, no, r; float ew;
    if (m < EE) {
        ni = node_in[m]; no = node_out[m]; r = relation[m]; ew = edge_weight[m];
    } else {
        ni = no = m - EE; r = RP1 - 1; ew = 1.f;
    }
    int pos = g_off[no] + atomicAdd(&g_cnt2[no], 1);
    g_erec[pos] = make_uint2((uint32_t)ni | ((uint32_t)r << 16), __float_as_uint(ew));
}

// ---------------------------------------------------------------------------
// Kg: mma.sync bf16 GEMM, frag-direct A. CTA = 128 nodes x 80 cols.
// ---------------------------------------------------------------------------
__global__ __launch_bounds__(128) void k_gemm(int dummy) {
    __shared__ uint4 sBf[1280];            // 20 KB

    const int r     = blockIdx.y;
    const int mbase = blockIdx.x * 128;
    const int tid   = threadIdx.x;
    const int w     = tid >> 5, lane = tid & 31;

    #pragma unroll
    for (int k = 0; k < 10; k++)
        sBf[tid + k * 128] = g_Bf[r * 1280 + tid + k * 128];

    uint4 af[2][8];
    const int gb = blockIdx.x * 8 + w * 2;
    #pragma unroll
    for (int i = 0; i < 2; i++)
        #pragma unroll
        for (int cb = 0; cb < 8; cb++)
            af[i][cb] = g_xa[((size_t)(gb + i) * 8 + cb) * 32 + lane];

    __syncthreads();

    float acc[2][40];
    #pragma unroll
    for (int i = 0; i < 2; i++)
        #pragma unroll
        for (int k = 0; k < 40; k++) acc[i][k] = 0.f;

    #pragma unroll
    for (int cb = 0; cb < 8; cb++) {
        uint4 bf[5];
        #pragma unroll
        for (int j = 0; j < 5; j++) bf[j] = sBf[(cb * 5 + j) * 32 + lane];

        const int nA = (cb < 4) ? 2 : 1;
        #pragma unroll
        for (int u = 0; u < 2; u++) {
            if (u < nA) {
                const int ca = (u == 0) ? ((cb < 4) ? cb : cb - 4) : cb + 4;
                #pragma unroll
                for (int i = 0; i < 2; i++)
                    #pragma unroll
                    for (int nt = 0; nt < 10; nt++) {
                        uint32_t b0 = (nt & 1) ? bf[nt >> 1].z : bf[nt >> 1].x;
                        uint32_t b1 = (nt & 1) ? bf[nt >> 1].w : bf[nt >> 1].y;
                        mma_bf16(acc[i] + nt * 4, af[i][ca].x, af[i][ca].y,
                                 af[i][ca].z, af[i][ca].w, b0, b1);
                    }
            }
        }
    }

    const int g = lane >> 2, t = lane & 3;
    #pragma unroll
    for (int i = 0; i < 2; i++)
        #pragma unroll
        for (int half = 0; half < 2; half++) {
            int n = mbase + w * 32 + i * 16 + g + 8 * half;
            if (n < NN) {
                uint32_t* hd = (uint32_t*)(g_hidden + ((size_t)r * NN + n) * 64 + 2 * t);
                #pragma unroll
                for (int nt = 0; nt < 8; nt++)
                    hd[nt * 4] = pack_h2(acc[i][nt * 4 + 2 * half],
                                         acc[i][nt * 4 + 2 * half + 1]);
                uint32_t* sd = (uint32_t*)(g_s + ((size_t)r * NN + n) * 16 + 2 * t);
                #pragma unroll
                for (int nt = 8; nt < 10; nt++)
                    sd[(nt - 8) * 4] = pack_h2(acc[i][nt * 4 + 2 * half],
                                               acc[i][nt * 4 + 2 * half + 1]);
            }
        }
}

// ---------------------------------------------------------------------------
// Ka: gather-side aggregation. One warp per destination node; lanes own dims
//   (2l, 2l+1). Per edge: broadcast record, per-lane logit from g_s, one
//   128-B h_in line, fp32 register accumulation. Fused normalize+ReLU+store.
//   No atomics.
// ---------------------------------------------------------------------------
__global__ __launch_bounds__(256) void k_agg(float* __restrict__ out) {
    const int n = blockIdx.x * 8 + (threadIdx.x >> 5);
    if (n >= NN) return;
    const int lane = threadIdx.x & 31;
    const int h = lane >> 2;

    const int start = g_off[n];
    const int end   = g_off[n + 1];

    float acc0 = 0.f, acc1 = 0.f, esum = 0.f;

    uint2 rec = (start < end) ? g_erec[start] : make_uint2(0u, 0u);
    for (int e = start; e < end; e++) {
        uint2 cur = rec;
        if (e + 1 < end) rec = g_erec[e + 1];   // prefetch next

        const int ni = (int)(cur.x & 0xFFFFu);
        const int r  = (int)(cur.x >> 16);
        const float ew = __uint_as_float(cur.y);

        const size_t bi = (size_t)r * NN + ni;
        const size_t bo = (size_t)r * NN + n;
        float w = __half2float(g_s[bi * 16 + h]) + __half2float(g_s[bo * 16 + 8 + h]);
        w = (w > 0.f) ? w : NEG_SLOPE * w;
        const float ee = __expf(w) * ew;

        const uint32_t hv = *(const uint32_t*)(g_hidden + bi * 64 + 2 * lane);
        const float2 f = __half22float2(*(const __half2*)&hv);
        acc0 += ee * f.x;
        acc1 += ee * f.y;
        esum += ee;
    }

    const float inv = 1.f / esum;          // every node has >=1 edge (self-loop)
    float o0 = acc0 * inv, o1 = acc1 * inv;
    o0 = (o0 > 0.f) ? o0 : 0.f;
    o1 = (o1 > 0.f) ? o1 : 0.f;
    *(float2*)(out + (size_t)n * 64 + 2 * lane) = make_float2(o0, o1);
}

// ---------------------------------------------------------------------------
extern "C" void kernel_launch(void* const* d_in, const int* in_sizes, int n_in,
                              void* d_out, int out_size) {
    const float* x           = (const float*)d_in[0];
    const float* W_tau       = (const float*)d_in[1];
    const float* query       = (const float*)d_in[2];
    const int*   node_in     = (const int*)  d_in[3];
    const int*   node_out    = (const int*)  d_in[4];
    const int*   relation    = (const int*)  d_in[5];
    const float* edge_weight = (const float*)d_in[6];

    k_zero<<<(NN + 255) / 256, 256>>>();
    k_prepX<<<(G16 * 4 * 32 + 255) / 256, 256>>>(x);
    k_prepWB<<<RP1, 256>>>(W_tau, query);

    // CSR sort by destination
    k_hist<<<(MM + 255) / 256, 256>>>(node_out);
    k_scan1<<<SB1, 256>>>();
    k_scan2<<<1, 256>>>();
    k_scan3<<<SB1, 256>>>();
    k_scatter<<<(MM + 255) / 256, 256>>>(node_in, node_out, relation, edge_weight);

    // node transform (tensor cores)
    dim3 gg(MT2, RP1);
    k_gemm<<<gg, 128>>>(0);

    // gather-side aggregation, fused finalize
    k_agg<<<(NN + 7) / 8, 256>>>((float*)d_out);
}